// round 3
// baseline (speedup 1.0000x reference)
#include <cuda_runtime.h>

// ZNCC fused, warp-resident sliding-window version. No shared memory, no CTA
// barriers. Each warp: 64 raw columns (2/lane) x 32-output-row strip, loops
// 3 channels, accumulates channel mean into out via RMW (same warp owns the
// pixels across channels -> deterministic).
//
// math per pixel (zero-padded 5x5 means):
//   mx = box(x), my = box(y); xc = x-mx, yc = y-my (forced 0 outside image)
//   ncc = Sxy / (sqrt(Sxx*Syy) + 25e-8),  S* = 5x5 sums of products
//   out = mean_c(ncc)

#define HH 512
#define WW 512
#define CHAN 3
#define SSTRIP 32
#define NSTRIPS (HH / SSTRIP)          // 16
#define OUTCOLS 56
#define NGROUPS 10                     // 10*56 = 560 >= 512
#define NBATCH 16
#define WARPS_PER_CTA 4
#define NTASKS (NGROUPS * NSTRIPS * NBATCH)     // 2560
#define NCTAS  (NTASKS / WARPS_PER_CTA)         // 640

__global__ __launch_bounds__(128, 4)
void zncc_warp_kernel(const float* __restrict__ xg,
                      const float* __restrict__ yg,
                      float* __restrict__ outg)
{
    const unsigned FULL = 0xFFFFFFFFu;
    const int lane = threadIdx.x & 31;
    const int task = blockIdx.x * WARPS_PER_CTA + (threadIdx.x >> 5);

    const int b     = task / (NGROUPS * NSTRIPS);
    const int rem   = task - b * (NGROUPS * NSTRIPS);
    const int strip = rem / NGROUPS;
    const int g     = rem - strip * NGROUPS;

    const int r0  = strip * SSTRIP;
    const int gcA = g * OUTCOLS - 4 + 2 * lane;   // even
    const int gcB = gcA + 1;
    const float mA = (gcA >= 0 && gcA < WW) ? 1.0f : 0.0f;
    const float mB = (gcB >= 0 && gcB < WW) ? 1.0f : 0.0f;
    const bool outLane = (lane >= 2) && (lane <= 29) && (gcA < WW);
    const int gca_c = min(max(gcA, 0), WW - 2);   // clamped, float2-safe

    const float inv25 = 1.0f / 25.0f;
    const float inv3  = 1.0f / 3.0f;

    float* outp = outg + (size_t)b * (HH * WW);

    for (int ch = 0; ch < CHAN; ch++) {
        const float* xb = xg + (size_t)(b * CHAN + ch) * (HH * WW);
        const float* yb = yg + (size_t)(b * CHAN + ch) * (HH * WW);

        // ring buffers (indices static after unroll-by-5)
        float hxA[5], hxB[5], hyA[5], hyB[5];
        float qxyA[5], qxyB[5], qxxA[5], qxxB[5], qyyA[5], qyyB[5];
        #pragma unroll
        for (int i = 0; i < 5; i++) {
            hxA[i] = hxB[i] = hyA[i] = hyB[i] = 0.f;
            qxyA[i] = qxyB[i] = qxxA[i] = qxxB[i] = qyyA[i] = qyyB[i] = 0.f;
        }
        float sHxA = 0.f, sHxB = 0.f, sHyA = 0.f, sHyB = 0.f;
        float sQxyA = 0.f, sQxyB = 0.f, sQxxA = 0.f, sQxxB = 0.f, sQyyA = 0.f, sQyyB = 0.f;
        // 2-deep shift pipeline for raw center values (need row t-2 at step t)
        float pxA1 = 0.f, pxA2 = 0.f, pxB1 = 0.f, pxB2 = 0.f;
        float pyA1 = 0.f, pyA2 = 0.f, pyB1 = 0.f, pyB2 = 0.f;

        for (int sb = 0; sb < SSTRIP + 8; sb += 5) {
            #pragma unroll
            for (int k = 0; k < 5; k++) {
                const int s = sb + k;                 // s % 5 == k
                const int t = r0 - 4 + s;             // raw row loaded now

                // ---- load raw row t (zero outside image) ----
                float vxA = 0.f, vxB = 0.f, vyA = 0.f, vyB = 0.f;
                if (t >= 0 && t < HH) {               // warp-uniform branch
                    const float2 vx = *(const float2*)(xb + (size_t)t * WW + gca_c);
                    const float2 vy = *(const float2*)(yb + (size_t)t * WW + gca_c);
                    vxA = vx.x * mA; vxB = vx.y * mB;
                    vyA = vy.x * mA; vyB = vy.y * mB;
                }

                // ---- horizontal 5-sums of x,y via shuffles ----
                float vxAm = __shfl_up_sync(FULL, vxA, 1);
                float vxBm = __shfl_up_sync(FULL, vxB, 1);
                float vxAp = __shfl_down_sync(FULL, vxA, 1);
                float vxBp = __shfl_down_sync(FULL, vxB, 1);
                float cx   = vxBm + vxA + vxB + vxAp;
                float hxEn = cx + vxAm;               // col A (2l)
                float hxOn = cx + vxBp;               // col B (2l+1)

                float vyAm = __shfl_up_sync(FULL, vyA, 1);
                float vyBm = __shfl_up_sync(FULL, vyB, 1);
                float vyAp = __shfl_down_sync(FULL, vyA, 1);
                float vyBp = __shfl_down_sync(FULL, vyB, 1);
                float cy   = vyBm + vyA + vyB + vyAp;
                float hyEn = cy + vyAm;
                float hyOn = cy + vyBp;

                // ---- vertical sliding sums of h ----
                sHxA += hxEn - hxA[k]; hxA[k] = hxEn;
                sHxB += hxOn - hxB[k]; hxB[k] = hxOn;
                sHyA += hyEn - hyA[k]; hyA[k] = hyEn;
                sHyB += hyOn - hyB[k]; hyB[k] = hyOn;

                if (s >= 4) {
                    const int tm = t - 2;             // row whose mean is ready
                    const float rm = (tm >= 0 && tm < HH) ? 1.0f : 0.0f;

                    // centered values at row tm (raw from 2 steps ago)
                    float xcA = fmaf(sHxA, -inv25, pxA2) * (mA * rm);
                    float xcB = fmaf(sHxB, -inv25, pxB2) * (mB * rm);
                    float ycA = fmaf(sHyA, -inv25, pyA2) * (mA * rm);
                    float ycB = fmaf(sHyB, -inv25, pyB2) * (mB * rm);

                    // neighbors of xc,yc
                    float xcAm = __shfl_up_sync(FULL, xcA, 1);
                    float xcBm = __shfl_up_sync(FULL, xcB, 1);
                    float xcAp = __shfl_down_sync(FULL, xcA, 1);
                    float xcBp = __shfl_down_sync(FULL, xcB, 1);
                    float ycAm = __shfl_up_sync(FULL, ycA, 1);
                    float ycBm = __shfl_up_sync(FULL, ycB, 1);
                    float ycAp = __shfl_down_sync(FULL, ycA, 1);
                    float ycBp = __shfl_down_sync(FULL, ycB, 1);

                    // horizontal 5-sums of products (shared middle-4 term)
                    float c4xy = xcBm * ycBm + xcA * ycA + xcB * ycB + xcAp * ycAp;
                    float qxyE = c4xy + xcAm * ycAm;
                    float qxyO = c4xy + xcBp * ycBp;
                    float c4xx = xcBm * xcBm + xcA * xcA + xcB * xcB + xcAp * xcAp;
                    float qxxE = c4xx + xcAm * xcAm;
                    float qxxO = c4xx + xcBp * xcBp;
                    float c4yy = ycBm * ycBm + ycA * ycA + ycB * ycB + ycAp * ycAp;
                    float qyyE = c4yy + ycAm * ycAm;
                    float qyyO = c4yy + ycBp * ycBp;

                    // vertical sliding sums of q
                    sQxyA += qxyE - qxyA[k]; qxyA[k] = qxyE;
                    sQxyB += qxyO - qxyB[k]; qxyB[k] = qxyO;
                    sQxxA += qxxE - qxxA[k]; qxxA[k] = qxxE;
                    sQxxB += qxxO - qxxB[k]; qxxB[k] = qxxO;
                    sQyyA += qyyE - qyyA[k]; qyyA[k] = qyyE;
                    sQyyB += qyyO - qyyB[k]; qyyB[k] = qyyO;

                    if (s >= 8) {
                        const int ro = r0 + s - 8;    // output row ready
                        float dA = sqrtf(fmaxf(sQxxA * sQyyA, 0.f)) + 2.5e-7f;
                        float dB = sqrtf(fmaxf(sQxxB * sQyyB, 0.f)) + 2.5e-7f;
                        float nA = __fdividef(sQxyA, dA) * inv3;
                        float nB = __fdividef(sQxyB, dB) * inv3;
                        if (outLane) {
                            float2* po = (float2*)(outp + (size_t)ro * WW + gcA);
                            float2 v;
                            if (ch == 0) {
                                v.x = nA; v.y = nB;
                            } else {
                                float2 o = *po;
                                v.x = o.x + nA; v.y = o.y + nB;
                            }
                            *po = v;
                        }
                    }
                }

                // shift raw-center pipeline
                pxA2 = pxA1; pxA1 = vxA;
                pxB2 = pxB1; pxB1 = vxB;
                pyA2 = pyA1; pyA1 = vyA;
                pyB2 = pyB1; pyB1 = vyB;
            }
        }
    }
}

extern "C" void kernel_launch(void* const* d_in, const int* in_sizes, int n_in,
                              void* d_out, int out_size)
{
    const float* x = (const float*)d_in[0];
    const float* y = (const float*)d_in[1];
    float* out = (float*)d_out;

    zncc_warp_kernel<<<NCTAS, 32 * WARPS_PER_CTA>>>(x, y, out);
}

// round 4
// speedup vs baseline: 1.5092x; 1.5092x over previous
#include <cuda_runtime.h>

// ZNCC fused, warp-resident sliding-window version with software prefetch.
// Each warp: 64 raw columns (2/lane) x 32-output-row strip, loops 3 channels,
// accumulates channel mean into out via RMW (same warp owns the pixels).
//
// math per pixel (zero-padded 5x5 means):
//   mx = box(x), my = box(y); xc = x-mx, yc = y-my (forced 0 outside image)
//   ncc = Sxy / (sqrt(Sxx*Syy) + 25e-8),  S* = 5x5 sums of products
//   out = mean_c(ncc)

#define HH 512
#define WW 512
#define CHAN 3
#define SSTRIP 32
#define NSTRIPS (HH / SSTRIP)          // 16
#define OUTCOLS 56
#define NGROUPS 10                     // 10*56 = 560 >= 512
#define NBATCH 16
#define WARPS_PER_CTA 4
#define NTASKS (NGROUPS * NSTRIPS * NBATCH)     // 2560
#define NCTAS  (NTASKS / WARPS_PER_CTA)         // 640

__global__ __launch_bounds__(128, 5)
void zncc_warp_kernel(const float* __restrict__ xg,
                      const float* __restrict__ yg,
                      float* __restrict__ outg)
{
    const unsigned FULL = 0xFFFFFFFFu;
    const int lane = threadIdx.x & 31;
    const int task = blockIdx.x * WARPS_PER_CTA + (threadIdx.x >> 5);

    const int b     = task / (NGROUPS * NSTRIPS);
    const int rem   = task - b * (NGROUPS * NSTRIPS);
    const int strip = rem / NGROUPS;
    const int g     = rem - strip * NGROUPS;

    const int r0  = strip * SSTRIP;
    const int gcA = g * OUTCOLS - 4 + 2 * lane;   // even
    const int gcB = gcA + 1;
    const float mA = (gcA >= 0 && gcA < WW) ? 1.0f : 0.0f;
    const float mB = (gcB >= 0 && gcB < WW) ? 1.0f : 0.0f;
    const bool outLane = (lane >= 2) && (lane <= 29) && (gcA < WW);
    const int gca_c = min(max(gcA, 0), WW - 2);   // clamped, float2-safe

    const float inv25 = 1.0f / 25.0f;
    const float inv3  = 1.0f / 3.0f;

    float* outp = outg + (size_t)b * (HH * WW);

    for (int ch = 0; ch < CHAN; ch++) {
        const float* xb = xg + (size_t)(b * CHAN + ch) * (HH * WW);
        const float* yb = yg + (size_t)(b * CHAN + ch) * (HH * WW);

        // ring buffers (indices static after unroll-by-5)
        float hxA[5], hxB[5], hyA[5], hyB[5];
        float qxyA[5], qxyB[5], qxxA[5], qxxB[5], qyyA[5], qyyB[5];
        #pragma unroll
        for (int i = 0; i < 5; i++) {
            hxA[i] = hxB[i] = hyA[i] = hyB[i] = 0.f;
            qxyA[i] = qxyB[i] = qxxA[i] = qxxB[i] = qyyA[i] = qyyB[i] = 0.f;
        }
        float sHxA = 0.f, sHxB = 0.f, sHyA = 0.f, sHyB = 0.f;
        float sQxyA = 0.f, sQxyB = 0.f, sQxxA = 0.f, sQxxB = 0.f, sQyyA = 0.f, sQyyB = 0.f;
        // 2-deep shift pipeline for raw center values (need row t-2 at step t)
        float pxA1 = 0.f, pxA2 = 0.f, pxB1 = 0.f, pxB2 = 0.f;
        float pyA1 = 0.f, pyA2 = 0.f, pyB1 = 0.f, pyB2 = 0.f;

        // staged next-row values (software prefetch)
        float2 nvx = make_float2(0.f, 0.f), nvy = make_float2(0.f, 0.f);
        {
            const int t0 = r0 - 4;
            if (t0 >= 0) {   // t0 < HH always
                nvx = *(const float2*)(xb + (size_t)t0 * WW + gca_c);
                nvy = *(const float2*)(yb + (size_t)t0 * WW + gca_c);
            }
        }

        for (int sb = 0; sb < SSTRIP + 8; sb += 5) {
            #pragma unroll
            for (int k = 0; k < 5; k++) {
                const int s = sb + k;                 // s % 5 == k
                const int t = r0 - 4 + s;             // raw row consumed now

                // ---- consume staged row t, issue loads for row t+1 ----
                float vxA = nvx.x * mA, vxB = nvx.y * mB;
                float vyA = nvy.x * mA, vyB = nvy.y * mB;
                {
                    const int tn = t + 1;             // warp-uniform
                    if (tn >= 0 && tn < HH) {
                        nvx = *(const float2*)(xb + (size_t)tn * WW + gca_c);
                        nvy = *(const float2*)(yb + (size_t)tn * WW + gca_c);
                    } else {
                        nvx = make_float2(0.f, 0.f);
                        nvy = make_float2(0.f, 0.f);
                    }
                }
                if (t < 0) { vxA = vxB = vyA = vyB = 0.f; }  // below-image rows

                // ---- horizontal 5-sums of x,y via shuffles ----
                float vxAm = __shfl_up_sync(FULL, vxA, 1);
                float vxBm = __shfl_up_sync(FULL, vxB, 1);
                float vxAp = __shfl_down_sync(FULL, vxA, 1);
                float vxBp = __shfl_down_sync(FULL, vxB, 1);
                float cx   = vxBm + vxA + vxB + vxAp;
                float hxEn = cx + vxAm;               // col A (2l)
                float hxOn = cx + vxBp;               // col B (2l+1)

                float vyAm = __shfl_up_sync(FULL, vyA, 1);
                float vyBm = __shfl_up_sync(FULL, vyB, 1);
                float vyAp = __shfl_down_sync(FULL, vyA, 1);
                float vyBp = __shfl_down_sync(FULL, vyB, 1);
                float cy   = vyBm + vyA + vyB + vyAp;
                float hyEn = cy + vyAm;
                float hyOn = cy + vyBp;

                // ---- vertical sliding sums of h ----
                sHxA += hxEn - hxA[k]; hxA[k] = hxEn;
                sHxB += hxOn - hxB[k]; hxB[k] = hxOn;
                sHyA += hyEn - hyA[k]; hyA[k] = hyEn;
                sHyB += hyOn - hyB[k]; hyB[k] = hyOn;

                if (s >= 4) {
                    const int tm = t - 2;             // row whose mean is ready
                    const float rm = (tm >= 0 && tm < HH) ? 1.0f : 0.0f;

                    // centered values at row tm (raw from 2 steps ago)
                    float xcA = fmaf(sHxA, -inv25, pxA2) * (mA * rm);
                    float xcB = fmaf(sHxB, -inv25, pxB2) * (mB * rm);
                    float ycA = fmaf(sHyA, -inv25, pyA2) * (mA * rm);
                    float ycB = fmaf(sHyB, -inv25, pyB2) * (mB * rm);

                    // neighbors of xc,yc
                    float xcAm = __shfl_up_sync(FULL, xcA, 1);
                    float xcBm = __shfl_up_sync(FULL, xcB, 1);
                    float xcAp = __shfl_down_sync(FULL, xcA, 1);
                    float xcBp = __shfl_down_sync(FULL, xcB, 1);
                    float ycAm = __shfl_up_sync(FULL, ycA, 1);
                    float ycBm = __shfl_up_sync(FULL, ycB, 1);
                    float ycAp = __shfl_down_sync(FULL, ycA, 1);
                    float ycBp = __shfl_down_sync(FULL, ycB, 1);

                    // horizontal 5-sums of products (shared middle-4 term)
                    float c4xy = xcBm * ycBm + xcA * ycA + xcB * ycB + xcAp * ycAp;
                    float qxyE = c4xy + xcAm * ycAm;
                    float qxyO = c4xy + xcBp * ycBp;
                    float c4xx = xcBm * xcBm + xcA * xcA + xcB * xcB + xcAp * xcAp;
                    float qxxE = c4xx + xcAm * xcAm;
                    float qxxO = c4xx + xcBp * xcBp;
                    float c4yy = ycBm * ycBm + ycA * ycA + ycB * ycB + ycAp * ycAp;
                    float qyyE = c4yy + ycAm * ycAm;
                    float qyyO = c4yy + ycBp * ycBp;

                    // vertical sliding sums of q
                    sQxyA += qxyE - qxyA[k]; qxyA[k] = qxyE;
                    sQxyB += qxyO - qxyB[k]; qxyB[k] = qxyO;
                    sQxxA += qxxE - qxxA[k]; qxxA[k] = qxxE;
                    sQxxB += qxxO - qxxB[k]; qxxB[k] = qxxO;
                    sQyyA += qyyE - qyyA[k]; qyyA[k] = qyyE;
                    sQyyB += qyyO - qyyB[k]; qyyB[k] = qyyO;

                    if (s >= 8) {
                        const int ro = r0 + s - 8;    // output row ready
                        float dA = sqrtf(fmaxf(sQxxA * sQyyA, 0.f)) + 2.5e-7f;
                        float dB = sqrtf(fmaxf(sQxxB * sQyyB, 0.f)) + 2.5e-7f;
                        float nA = __fdividef(sQxyA, dA) * inv3;
                        float nB = __fdividef(sQxyB, dB) * inv3;
                        if (outLane) {
                            float2* po = (float2*)(outp + (size_t)ro * WW + gcA);
                            float2 v;
                            if (ch == 0) {
                                v.x = nA; v.y = nB;
                            } else {
                                float2 o = *po;
                                v.x = o.x + nA; v.y = o.y + nB;
                            }
                            *po = v;
                        }
                    }
                }

                // shift raw-center pipeline
                pxA2 = pxA1; pxA1 = vxA;
                pxB2 = pxB1; pxB1 = vxB;
                pyA2 = pyA1; pyA1 = vyA;
                pyB2 = pyB1; pyB1 = vyB;
            }
        }
    }
}

extern "C" void kernel_launch(void* const* d_in, const int* in_sizes, int n_in,
                              void* d_out, int out_size)
{
    const float* x = (const float*)d_in[0];
    const float* y = (const float*)d_in[1];
    float* out = (float*)d_out;

    zncc_warp_kernel<<<NCTAS, 32 * WARPS_PER_CTA>>>(x, y, out);
}

// round 5
// speedup vs baseline: 2.0018x; 1.3264x over previous
#include <cuda_runtime.h>

// ZNCC fused, warp-per-channel sliding-window version.
// CTA = 96 threads = 3 warps; warp w handles channel w of one
// (batch, strip, col-group) tile: 64 raw cols (2/lane) x 32 output rows.
// Per-channel NCC rows go to an smem plane; after one __syncthreads the CTA
// combines the 3 planes in fixed order (deterministic) and writes out.
//
// math per pixel (zero-padded 5x5 means):
//   mx = box(x), my = box(y); xc = x-mx, yc = y-my (forced 0 outside image)
//   ncc = Sxy / (sqrt(Sxx*Syy) + 25e-8),  S* = 5x5 sums of products
//   out = mean_c(ncc)

#define HH 512
#define WW 512
#define CHAN 3
#define SSTRIP 32
#define NSTRIPS (HH / SSTRIP)          // 16
#define OUTCOLS 56
#define NGROUPS 10                     // 10*56 = 560 >= 512
#define NBATCH 16
#define NCTAS (NGROUPS * NSTRIPS * NBATCH)   // 2560
#define PSTRIDE 58                     // plane row stride (even -> float2 STS)

__global__ __launch_bounds__(96, 7)
void zncc_warp_kernel(const float* __restrict__ xg,
                      const float* __restrict__ yg,
                      float* __restrict__ outg)
{
    __shared__ float plane[CHAN][SSTRIP][PSTRIDE];

    const unsigned FULL = 0xFFFFFFFFu;
    const int tid  = threadIdx.x;
    const int lane = tid & 31;
    const int ch   = tid >> 5;          // warp id == channel

    const int task  = blockIdx.x;
    const int b     = task / (NGROUPS * NSTRIPS);
    const int rem   = task - b * (NGROUPS * NSTRIPS);
    const int strip = rem / NGROUPS;
    const int g     = rem - strip * NGROUPS;

    const int r0  = strip * SSTRIP;
    const int gcA = g * OUTCOLS - 4 + 2 * lane;   // even
    const int gcB = gcA + 1;
    const float mA = (gcA >= 0 && gcA < WW) ? 1.0f : 0.0f;
    const float mB = (gcB >= 0 && gcB < WW) ? 1.0f : 0.0f;
    const bool outLane = (lane >= 2) && (lane <= 29) && (gcA < WW);
    const int gca_c = min(max(gcA, 0), WW - 2);   // clamped, float2-safe
    const int pcol  = 2 * lane - 4;               // plane column for col A

    const float inv25 = 1.0f / 25.0f;
    const float inv3  = 1.0f / 3.0f;

    const float* xb = xg + (size_t)(b * CHAN + ch) * (HH * WW);
    const float* yb = yg + (size_t)(b * CHAN + ch) * (HH * WW);

    // ring buffers (indices static after unroll-by-5)
    float hxA[5], hxB[5], hyA[5], hyB[5];
    float qxyA[5], qxyB[5], qxxA[5], qxxB[5], qyyA[5], qyyB[5];
    #pragma unroll
    for (int i = 0; i < 5; i++) {
        hxA[i] = hxB[i] = hyA[i] = hyB[i] = 0.f;
        qxyA[i] = qxyB[i] = qxxA[i] = qxxB[i] = qyyA[i] = qyyB[i] = 0.f;
    }
    float sHxA = 0.f, sHxB = 0.f, sHyA = 0.f, sHyB = 0.f;
    float sQxyA = 0.f, sQxyB = 0.f, sQxxA = 0.f, sQxxB = 0.f, sQyyA = 0.f, sQyyB = 0.f;
    // 2-deep shift pipeline for raw center values (need row t-2 at step t)
    float pxA1 = 0.f, pxA2 = 0.f, pxB1 = 0.f, pxB2 = 0.f;
    float pyA1 = 0.f, pyA2 = 0.f, pyB1 = 0.f, pyB2 = 0.f;

    // staged next-row values (software prefetch)
    float2 nvx = make_float2(0.f, 0.f), nvy = make_float2(0.f, 0.f);
    {
        const int t0 = r0 - 4;
        if (t0 >= 0) {
            nvx = *(const float2*)(xb + (size_t)t0 * WW + gca_c);
            nvy = *(const float2*)(yb + (size_t)t0 * WW + gca_c);
        }
    }

    for (int sb = 0; sb < SSTRIP + 8; sb += 5) {
        #pragma unroll
        for (int k = 0; k < 5; k++) {
            const int s = sb + k;                 // s % 5 == k
            const int t = r0 - 4 + s;             // raw row consumed now

            // ---- consume staged row t, issue loads for row t+1 ----
            float vxA = nvx.x * mA, vxB = nvx.y * mB;
            float vyA = nvy.x * mA, vyB = nvy.y * mB;
            {
                const int tn = t + 1;             // warp-uniform
                if (tn >= 0 && tn < HH) {
                    nvx = *(const float2*)(xb + (size_t)tn * WW + gca_c);
                    nvy = *(const float2*)(yb + (size_t)tn * WW + gca_c);
                } else {
                    nvx = make_float2(0.f, 0.f);
                    nvy = make_float2(0.f, 0.f);
                }
            }
            if (t < 0) { vxA = vxB = vyA = vyB = 0.f; }  // above-image rows

            // ---- horizontal 5-sums of x,y via shuffles ----
            float vxAm = __shfl_up_sync(FULL, vxA, 1);
            float vxBm = __shfl_up_sync(FULL, vxB, 1);
            float vxAp = __shfl_down_sync(FULL, vxA, 1);
            float vxBp = __shfl_down_sync(FULL, vxB, 1);
            float cx   = vxBm + vxA + vxB + vxAp;
            float hxEn = cx + vxAm;               // col A (2l)
            float hxOn = cx + vxBp;               // col B (2l+1)

            float vyAm = __shfl_up_sync(FULL, vyA, 1);
            float vyBm = __shfl_up_sync(FULL, vyB, 1);
            float vyAp = __shfl_down_sync(FULL, vyA, 1);
            float vyBp = __shfl_down_sync(FULL, vyB, 1);
            float cy   = vyBm + vyA + vyB + vyAp;
            float hyEn = cy + vyAm;
            float hyOn = cy + vyBp;

            // ---- vertical sliding sums of h ----
            sHxA += hxEn - hxA[k]; hxA[k] = hxEn;
            sHxB += hxOn - hxB[k]; hxB[k] = hxOn;
            sHyA += hyEn - hyA[k]; hyA[k] = hyEn;
            sHyB += hyOn - hyB[k]; hyB[k] = hyOn;

            if (s >= 4) {
                const int tm = t - 2;             // row whose mean is ready
                const float rm = (tm >= 0 && tm < HH) ? 1.0f : 0.0f;

                // centered values at row tm (raw from 2 steps ago)
                float xcA = fmaf(sHxA, -inv25, pxA2) * (mA * rm);
                float xcB = fmaf(sHxB, -inv25, pxB2) * (mB * rm);
                float ycA = fmaf(sHyA, -inv25, pyA2) * (mA * rm);
                float ycB = fmaf(sHyB, -inv25, pyB2) * (mB * rm);

                // neighbors of xc,yc
                float xcAm = __shfl_up_sync(FULL, xcA, 1);
                float xcBm = __shfl_up_sync(FULL, xcB, 1);
                float xcAp = __shfl_down_sync(FULL, xcA, 1);
                float xcBp = __shfl_down_sync(FULL, xcB, 1);
                float ycAm = __shfl_up_sync(FULL, ycA, 1);
                float ycBm = __shfl_up_sync(FULL, ycB, 1);
                float ycAp = __shfl_down_sync(FULL, ycA, 1);
                float ycBp = __shfl_down_sync(FULL, ycB, 1);

                // horizontal 5-sums of products (shared middle-4 term)
                float c4xy = xcBm * ycBm + xcA * ycA + xcB * ycB + xcAp * ycAp;
                float qxyE = c4xy + xcAm * ycAm;
                float qxyO = c4xy + xcBp * ycBp;
                float c4xx = xcBm * xcBm + xcA * xcA + xcB * xcB + xcAp * xcAp;
                float qxxE = c4xx + xcAm * xcAm;
                float qxxO = c4xx + xcBp * xcBp;
                float c4yy = ycBm * ycBm + ycA * ycA + ycB * ycB + ycAp * ycAp;
                float qyyE = c4yy + ycAm * ycAm;
                float qyyO = c4yy + ycBp * ycBp;

                // vertical sliding sums of q
                sQxyA += qxyE - qxyA[k]; qxyA[k] = qxyE;
                sQxyB += qxyO - qxyB[k]; qxyB[k] = qxyO;
                sQxxA += qxxE - qxxA[k]; qxxA[k] = qxxE;
                sQxxB += qxxO - qxxB[k]; qxxB[k] = qxxO;
                sQyyA += qyyE - qyyA[k]; qyyA[k] = qyyE;
                sQyyB += qyyO - qyyB[k]; qyyB[k] = qyyO;

                if (s >= 8) {
                    const int row = s - 8;        // output row within strip
                    float dA = sqrtf(fmaxf(sQxxA * sQyyA, 0.f)) + 2.5e-7f;
                    float dB = sqrtf(fmaxf(sQxxB * sQyyB, 0.f)) + 2.5e-7f;
                    float nA = __fdividef(sQxyA, dA);
                    float nB = __fdividef(sQxyB, dB);
                    if (outLane) {
                        *(float2*)&plane[ch][row][pcol] = make_float2(nA, nB);
                    }
                }
            }

            // shift raw-center pipeline
            pxA2 = pxA1; pxA1 = vxA;
            pxB2 = pxB1; pxB1 = vxB;
            pyA2 = pyA1; pyA1 = vyA;
            pyB2 = pyB1; pyB1 = vyB;
        }
    }

    __syncthreads();

    // ---- combine channels in fixed order (deterministic) and write out ----
    float* outp = outg + (size_t)b * (HH * WW) + (size_t)r0 * WW + g * OUTCOLS;
    for (int idx = tid; idx < SSTRIP * OUTCOLS; idx += 96) {
        int row = idx / OUTCOLS;
        int c   = idx - row * OUTCOLS;
        if (g * OUTCOLS + c < WW) {
            float v = (plane[0][row][c] + plane[1][row][c] + plane[2][row][c]) * inv3;
            outp[(size_t)row * WW + c] = v;
        }
    }
}

extern "C" void kernel_launch(void* const* d_in, const int* in_sizes, int n_in,
                              void* d_out, int out_size)
{
    const float* x = (const float*)d_in[0];
    const float* y = (const float*)d_in[1];
    float* out = (float*)d_out;

    zncc_warp_kernel<<<NCTAS, 96>>>(x, y, out);
}